// round 5
// baseline (speedup 1.0000x reference)
#include <cuda_runtime.h>
#include <cuda_bf16.h>

#define Hcst   1024
#define Dcst   128
#define TPcst  48
#define NBcst  384
#define Ecst   16384
#define EHcst  17408
#define OUTHALF 196608

typedef unsigned long long u64;

// ---------------- device scratch ----------------
__device__ u64    g_Xh[NBcst*Hcst];      // 3.1 MB : bf16x4 taps per (b,node)
__device__ int    g_rowptr[Hcst+1];
__device__ int    g_cursor[Hcst];
__device__ float  g_deg[Hcst];
__device__ unsigned g_pk[EHcst];         // (bf16 coef)<<16 | col
__device__ float  g_rowsum[Hcst];
__device__ float  g_S[4*Hcst];
__device__ int    g_invgrp[Hcst];
__device__ float  g_WW1[4*Dcst];
__device__ float  g_bb1[Dcst];
__device__ float  g_time[NBcst*Dcst];
__device__ float  g_tcwT[512*Dcst];      // 256 KB : tcw transposed, [j][d]

// ---------------- helpers ----------------
__device__ __forceinline__ u64 pk2(float lo, float hi) {
    u64 r; asm("mov.b64 %0,{%1,%2};" : "=l"(r) : "f"(lo), "f"(hi)); return r;
}
__device__ __forceinline__ void upk2(u64 v, float& lo, float& hi) {
    asm("mov.b64 {%0,%1},%2;" : "=f"(lo), "=f"(hi) : "l"(v));
}
__device__ __forceinline__ u64 fma2(u64 a, u64 b, u64 c) {
    u64 d; asm("fma.rn.f32x2 %0,%1,%2,%3;" : "=l"(d) : "l"(a), "l"(b), "l"(c)); return d;
}
__device__ __forceinline__ u64 pkbf4(float a, float b, float c, float d) {
    return (u64)__bfloat16_as_ushort(__float2bfloat16(a))
         | ((u64)__bfloat16_as_ushort(__float2bfloat16(b)) << 16)
         | ((u64)__bfloat16_as_ushort(__float2bfloat16(c)) << 32)
         | ((u64)__bfloat16_as_ushort(__float2bfloat16(d)) << 48);
}

// ================= k1 : prep + tcw transpose + X4 transpose =================
__global__ void __launch_bounds__(1024) k1(const void* ed, const void* ns,
        const float* x, const float* tcw,
        const float* tvw, const float* tvb, const float* W1) {
    int t = threadIdx.x, blk = blockIdx.x;
    if (blk == 0) {
        // edge count + exclusive scan + deg + rowptr
        __shared__ int sflag; __shared__ int cnt[Hcst]; __shared__ int wsum[32];
        if (t == 0) sflag = 1;
        __syncthreads();
        if (t < 64) { if (((const int*)ed)[2*t+1] != 0) atomicAnd(&sflag, 0); }
        cnt[t] = 1;
        __syncthreads();
        int f = sflag;
        for (int i = t; i < Ecst; i += 1024) {
            int d = f ? (int)((const long long*)ed)[2L*i+1] : ((const int*)ed)[2*i+1];
            atomicAdd(&cnt[d], 1);
        }
        __syncthreads();
        int c = cnt[t];
        int lane = t & 31, wid = t >> 5;
        int v = c;
        #pragma unroll
        for (int o = 1; o < 32; o <<= 1) { int uu = __shfl_up_sync(~0u, v, o); if (lane >= o) v += uu; }
        if (lane == 31) wsum[wid] = v;
        __syncthreads();
        if (wid == 0) {
            int w = wsum[lane];
            #pragma unroll
            for (int o = 1; o < 32; o <<= 1) { int uu = __shfl_up_sync(~0u, w, o); if (lane >= o) w += uu; }
            wsum[lane] = w;
        }
        __syncthreads();
        int incl = v + (wid > 0 ? wsum[wid-1] : 0);
        g_rowptr[t] = incl - c;
        g_cursor[t] = incl - c;
        g_deg[t]    = (float)c;
        if (t == 1023) g_rowptr[Hcst] = incl;
    } else if (blk == 1) {
        __shared__ int sflag;
        if (t == 0) sflag = 1;
        __syncthreads();
        if (t < 64) { if (((const int*)ns)[2*t+1] != 0) atomicAnd(&sflag, 0); }
        __syncthreads();
        int v = sflag ? (int)((const long long*)ns)[t] : ((const int*)ns)[t];
        g_invgrp[v] = t >> 8;
    } else if (blk == 2) {
        if (t < 512) {
            int k = t >> 7, e = t & 127;
            float acc = 0.f;
            for (int d = 0; d < Dcst; d++) acc += tvw[d*4 + k] * W1[d*Dcst + e];
            g_WW1[k*Dcst + e] = acc;
        } else if (t < 640) {
            int e = t - 512;
            float bsum = 0.f;
            for (int d = 0; d < Dcst; d++) bsum += tvb[d] * W1[d*Dcst + e];
            g_bb1[e] = bsum;
        }
    } else if (blk == 3) {
        for (int i = t; i < 4*Hcst; i += 1024) g_S[i] = 0.f;
        if (t < Hcst) g_rowsum[t] = 0.f;
    } else if (blk < 68) {
        // tcw transpose: 64 blocks x 1024 elements (coalesced read, scattered write)
        int idx = (blk - 4)*1024 + t;        // 65536 total
        int d = idx >> 9, j = idx & 511;
        g_tcwT[j*Dcst + d] = tcw[idx];
    } else {
        // X4 transpose -> packed bf16x4, 4 b's per block (blocks 68..163)
        int sub = t >> 8, tl = t & 255;
        int b = (blk - 68)*4 + sub, n = b / TPcst, tp = b % TPcst;
        const float4* xr = (const float4*)(x + ((long)(n*192 + tp*4))*Hcst);
        float4 r0 = xr[tl], r1 = xr[256+tl], r2 = xr[512+tl], r3 = xr[768+tl];
        u64* dst = g_Xh + (long)b*Hcst + tl*4;
        dst[0] = pkbf4(r0.x, r1.x, r2.x, r3.x);
        dst[1] = pkbf4(r0.y, r1.y, r2.y, r3.y);
        dst[2] = pkbf4(r0.z, r1.z, r2.z, r3.z);
        dst[3] = pkbf4(r0.w, r1.w, r2.w, r3.w);
    }
}

// ================= k2 : CSR fill + time embedding =================
__global__ void __launch_bounds__(512) k2(const void* ed, const void* xm,
        const float* hemb, const float* wemb, const float* tcb, float* out) {
    int t = threadIdx.x, blk = blockIdx.x;
    if (blk < 34) {
        // CSR fill (+rowsum, +S): 34 x 512 = 17408 = EHcst
        __shared__ int sflag;
        if (t == 0) sflag = 1;
        __syncthreads();
        if (t < 64) { if (((const int*)ed)[2*t+1] != 0) atomicAnd(&sflag, 0); }
        __syncthreads();
        int f = sflag;
        int i = blk*512 + t;
        int s, d;
        if (i < Ecst) {
            if (f) { s = (int)((const long long*)ed)[2L*i]; d = (int)((const long long*)ed)[2L*i+1]; }
            else   { s = ((const int*)ed)[2*i];             d = ((const int*)ed)[2*i+1]; }
        } else s = d = i - Ecst;
        float w = rsqrtf(g_deg[s]*g_deg[d]);
        int pos = atomicAdd(&g_cursor[d], 1);
        unsigned cb = (unsigned)__bfloat16_as_ushort(__float2bfloat16(w));
        g_pk[pos] = (unsigned)s | (cb << 16);
        atomicAdd(&g_rowsum[d], w);
        atomicAdd(&g_S[g_invgrp[d]*Hcst + s], w * (1.f/256.f));
    } else {
        // time embedding: 96 blocks x 4 b's, 512 threads (sub = t>>7, d = t&127)
        __shared__ int sflag;
        __shared__ float es[4][512];
        if (t == 0) sflag = 1;
        __syncthreads();
        if (t < 64) { if (((const int*)xm)[2*t+1] != 0) atomicAnd(&sflag, 0); }
        __syncthreads();
        int fm = sflag;
        int sub = t >> 7, tl = t & 127;
        int b = (blk - 34)*4 + sub, n = b / TPcst, tp = b % TPcst;
        for (int j = tl; j < 512; j += 128) {
            int k = j & 3, c = j >> 2;
            long base = ((long)(n*192 + tp*4 + k))*2;
            int ih, iw;
            if (fm) { ih = (int)((const long long*)xm)[base+1]; iw = (int)((const long long*)xm)[base]; }
            else    { ih = ((const int*)xm)[base+1];             iw = ((const int*)xm)[base]; }
            es[sub][j] = hemb[ih*Dcst + c] + wemb[iw*Dcst + c];
        }
        __syncthreads();
        int d = tl;
        float acc = tcb[d];
        #pragma unroll 4
        for (int j = 0; j < 512; j++)
            acc += es[sub][j] * g_tcwT[j*Dcst + d];
        g_time[b*Dcst + d] = acc;
        long ob = OUTHALF + ((long)(n*192 + tp*4))*Dcst + d;
        out[ob] = acc; out[ob+128] = acc; out[ob+256] = acc; out[ob+384] = acc;
    }
}

// ================= k3 : per-b gather + token + epilogue =================
__global__ void __launch_bounds__(256, 3) k3(const float* b1, const float* W2,
                                             const float* b2, float* out) {
    __shared__ u64        sXh[Hcst];     // 8 KB  bf16x4 taps
    __shared__ ulonglong2 sYA[512];      // 8 KB
    __shared__ ulonglong2 sYB[512];      // 8 KB
    __shared__ ulonglong2 sSI[Hcst];     // 16 KB
    __shared__ u64        sRSp[512];     // 4 KB
    __shared__ u64        sAcc[256][4];  // 8 KB
    __shared__ ulonglong2 sGM[128];      // 2 KB

    int t = threadIdx.x, b = blockIdx.x;
    int n = b / TPcst, tp = b % TPcst;

    for (int i = t; i < Hcst; i += 256) {
        sXh[i] = g_Xh[(long)b*Hcst + i];
        ulonglong2 e;
        e.x = pk2(g_S[i],        g_S[Hcst+i]);
        e.y = pk2(g_S[2*Hcst+i], g_S[3*Hcst+i]);
        sSI[i] = e;
    }
    for (int vp = t; vp < 512; vp += 256)
        sRSp[vp] = pk2(g_rowsum[2*vp], g_rowsum[2*vp+1]);
    __syncthreads();

    // ---- gather from SMEM (bf16 taps) ----
    #pragma unroll
    for (int rep = 0; rep < 2; rep++) {
        int vp = t + rep*256;
        float y[2][4];
        #pragma unroll
        for (int e = 0; e < 2; e++) {
            int v = 2*vp + e;
            int j0 = g_rowptr[v], j1 = g_rowptr[v+1];
            float a0=0.f, a1=0.f, a2=0.f, a3=0.f;
            for (int j = j0; j < j1; j++) {
                unsigned p = __ldg(&g_pk[j]);
                float w = __uint_as_float(p & 0xFFFF0000u);
                u64 xv = sXh[p & 1023u];
                float t0 = __uint_as_float((unsigned)(xv & 0xFFFFu) << 16);
                float t1 = __uint_as_float((unsigned)xv & 0xFFFF0000u);
                float t2 = __uint_as_float((unsigned)((xv >> 32) & 0xFFFFu) << 16);
                float t3 = __uint_as_float((unsigned)(xv >> 48) << 16);
                a0 += w*t0; a1 += w*t1; a2 += w*t2; a3 += w*t3;
            }
            y[e][0]=a0; y[e][1]=a1; y[e][2]=a2; y[e][3]=a3;
        }
        ulonglong2 ea, eb;
        ea.x = pk2(y[0][0], y[1][0]); ea.y = pk2(y[0][1], y[1][1]);
        eb.x = pk2(y[0][2], y[1][2]); eb.y = pk2(y[0][3], y[1][3]);
        sYA[vp] = ea; sYB[vp] = eb;
    }
    __syncthreads();

    // ---- token loop ----
    int dA = t & 63, dB = dA + 64;
    int q  = t >> 6;
    u64 W0A = pk2(g_WW1[dA],     g_WW1[dA]);
    u64 W1A = pk2(g_WW1[128+dA], g_WW1[128+dA]);
    u64 W2A = pk2(g_WW1[256+dA], g_WW1[256+dA]);
    u64 W3A = pk2(g_WW1[384+dA], g_WW1[384+dA]);
    u64 BBA = pk2(g_bb1[dA],     g_bb1[dA]);
    u64 B1A = pk2(b1[dA],        b1[dA]);
    u64 W0B = pk2(g_WW1[dB],     g_WW1[dB]);
    u64 W1B = pk2(g_WW1[128+dB], g_WW1[128+dB]);
    u64 W2B = pk2(g_WW1[256+dB], g_WW1[256+dB]);
    u64 W3B = pk2(g_WW1[384+dB], g_WW1[384+dB]);
    u64 BBB = pk2(g_bb1[dB],     g_bb1[dB]);
    u64 B1B = pk2(b1[dB],        b1[dB]);
    u64 a01A = 0, a23A = 0, a01B = 0, a23B = 0;
    int vp0 = q*128;
    #pragma unroll 2
    for (int vp = vp0; vp < vp0+128; vp++) {
        ulonglong2 ya = sYA[vp], yb = sYB[vp];
        u64 rsp = sRSp[vp];
        u64 hA = fma2(ya.x, W0A, B1A);
        hA = fma2(ya.y, W1A, hA);
        hA = fma2(yb.x, W2A, hA);
        hA = fma2(yb.y, W3A, hA);
        hA = fma2(rsp,  BBA, hA);
        u64 hB = fma2(ya.x, W0B, B1B);
        hB = fma2(ya.y, W1B, hB);
        hB = fma2(yb.x, W2B, hB);
        hB = fma2(yb.y, W3B, hB);
        hB = fma2(rsp,  BBB, hB);
        float ae, ao, be, bo;
        upk2(hA, ae, ao); upk2(hB, be, bo);
        ae = fmaxf(ae, 0.f); ao = fmaxf(ao, 0.f);
        be = fmaxf(be, 0.f); bo = fmaxf(bo, 0.f);
        u64 hAe = pk2(ae, ae), hAo = pk2(ao, ao);
        u64 hBe = pk2(be, be), hBo = pk2(bo, bo);
        ulonglong2 s0 = sSI[2*vp], s1 = sSI[2*vp+1];
        a01A = fma2(s0.x, hAe, a01A); a23A = fma2(s0.y, hAe, a23A);
        a01A = fma2(s1.x, hAo, a01A); a23A = fma2(s1.y, hAo, a23A);
        a01B = fma2(s0.x, hBe, a01B); a23B = fma2(s0.y, hBe, a23B);
        a01B = fma2(s1.x, hBo, a01B); a23B = fma2(s1.y, hBo, a23B);
    }
    sAcc[t][0] = a01A; sAcc[t][1] = a23A; sAcc[t][2] = a01B; sAcc[t][3] = a23B;
    __syncthreads();

    // ---- reduce quarters -> group sums (pre-W2) ----
    if (t < 128) {
        int d = t, lane = d & 63, hi = d >> 6;
        float g0=0.f, g1=0.f, g2=0.f, g3=0.f;
        #pragma unroll
        for (int qq = 0; qq < 4; qq++) {
            float x0, x1;
            upk2(sAcc[qq*64+lane][hi*2+0], x0, x1); g0 += x0; g1 += x1;
            upk2(sAcc[qq*64+lane][hi*2+1], x0, x1); g2 += x0; g3 += x1;
        }
        ulonglong2 e;
        e.x = pk2(g0, g1); e.y = pk2(g2, g3);
        sGM[d] = e;
    }
    __syncthreads();

    // ---- epilogue: out = gm @ W2 + b2 + time ----
    if (t < 128) {
        int d = t;
        u64 o01 = 0, o23 = 0;
        #pragma unroll 4
        for (int c = 0; c < 128; c++) {
            ulonglong2 g = sGM[c];
            float w = __ldg(&W2[c*Dcst + d]);
            u64 ws = pk2(w, w);
            o01 = fma2(g.x, ws, o01);
            o23 = fma2(g.y, ws, o23);
        }
        float o0, o1, o2, o3;
        upk2(o01, o0, o1); upk2(o23, o2, o3);
        float base = g_time[b*Dcst + d] + b2[d];
        long ob = ((long)(n*192 + tp*4))*Dcst + d;
        out[ob]     = o0 + base;
        out[ob+128] = o1 + base;
        out[ob+256] = o2 + base;
        out[ob+384] = o3 + base;
    }
}

// ---------------- launch ----------------
extern "C" void kernel_launch(void* const* d_in, const int* in_sizes, int n_in,
                              void* d_out, int out_size) {
    const float* x    = (const float*)d_in[0];
    const void*  xm   = d_in[1];
    const void*  ed   = d_in[2];
    const void*  ns   = d_in[3];
    const float* hemb = (const float*)d_in[4];
    const float* wemb = (const float*)d_in[5];
    const float* tcw  = (const float*)d_in[6];
    const float* tcb  = (const float*)d_in[7];
    const float* tvw  = (const float*)d_in[8];
    const float* tvb  = (const float*)d_in[9];
    const float* W1   = (const float*)d_in[10];
    const float* b1   = (const float*)d_in[11];
    const float* W2   = (const float*)d_in[12];
    const float* b2   = (const float*)d_in[13];
    float* out = (float*)d_out;

    k1<<<164, 1024>>>(ed, ns, x, tcw, tvw, tvb, W1);
    k2<<<130, 512>>>(ed, xm, hemb, wemb, tcb, out);
    k3<<<NBcst, 256>>>(b1, W2, b2, out);
}

// round 6
// speedup vs baseline: 1.6145x; 1.6145x over previous
#include <cuda_runtime.h>
#include <cuda_bf16.h>

#define Hcst   1024
#define Dcst   128
#define TPcst  48
#define NBcst  384
#define Ecst   16384
#define EHcst  17408
#define OUTHALF 196608
#define MAXDEG 64

typedef unsigned long long u64;

// ---------------- device scratch ----------------
__device__ u64      g_Xh[NBcst*Hcst];     // 3.1 MB bf16x4 taps
__device__ int      g_cursor[Hcst];
__device__ float    g_deg[Hcst];
__device__ int      g_degi[Hcst];
__device__ unsigned g_pkT[MAXDEG*Hcst];   // 256 KB transposed edges: [e][v]
__device__ float    g_rowsum[Hcst];
__device__ float    g_S[4*Hcst];
__device__ int      g_invgrp[Hcst];
__device__ float    g_WW1[4*Dcst];
__device__ float    g_bb1[Dcst];
__device__ float    g_tcwT[512*Dcst];     // 256 KB tcw transposed [j][d]
__device__ float    g_hpro[4*48*Dcst];    // 98 KB
__device__ float    g_wpro[4*7*Dcst];     // 14 KB

// ---------------- helpers ----------------
__device__ __forceinline__ u64 pk2(float lo, float hi) {
    u64 r; asm("mov.b64 %0,{%1,%2};" : "=l"(r) : "f"(lo), "f"(hi)); return r;
}
__device__ __forceinline__ void upk2(u64 v, float& lo, float& hi) {
    asm("mov.b64 {%0,%1},%2;" : "=f"(lo), "=f"(hi) : "l"(v));
}
__device__ __forceinline__ u64 fma2(u64 a, u64 b, u64 c) {
    u64 d; asm("fma.rn.f32x2 %0,%1,%2,%3;" : "=l"(d) : "l"(a), "l"(b), "l"(c)); return d;
}
__device__ __forceinline__ u64 pkbf4(float a, float b, float c, float d) {
    return (u64)__bfloat16_as_ushort(__float2bfloat16(a))
         | ((u64)__bfloat16_as_ushort(__float2bfloat16(b)) << 16)
         | ((u64)__bfloat16_as_ushort(__float2bfloat16(c)) << 32)
         | ((u64)__bfloat16_as_ushort(__float2bfloat16(d)) << 48);
}

// ================= k1 : degree count + prep + transposes =================
__global__ void __launch_bounds__(1024) k1(const void* ed, const void* ns,
        const float* x, const float* tcw,
        const float* tvw, const float* tvb, const float* W1) {
    int t = threadIdx.x, blk = blockIdx.x;
    if (blk == 0) {
        __shared__ int sflag; __shared__ int cnt[Hcst];
        if (t == 0) sflag = 1;
        __syncthreads();
        if (t < 64) { if (((const int*)ed)[2*t+1] != 0) atomicAnd(&sflag, 0); }
        cnt[t] = 1;      // self loop
        __syncthreads();
        int f = sflag;
        for (int i = t; i < Ecst; i += 1024) {
            int d = f ? (int)((const long long*)ed)[2L*i+1] : ((const int*)ed)[2*i+1];
            atomicAdd(&cnt[d], 1);
        }
        __syncthreads();
        g_deg[t]   = (float)cnt[t];
        g_degi[t]  = cnt[t];
        g_cursor[t] = 0;
    } else if (blk == 1) {
        __shared__ int sflag;
        if (t == 0) sflag = 1;
        __syncthreads();
        if (t < 64) { if (((const int*)ns)[2*t+1] != 0) atomicAnd(&sflag, 0); }
        __syncthreads();
        int v = sflag ? (int)((const long long*)ns)[t] : ((const int*)ns)[t];
        g_invgrp[v] = t >> 8;
    } else if (blk == 2) {
        if (t < 512) {
            int k = t >> 7, e = t & 127;
            float acc = 0.f;
            for (int d = 0; d < Dcst; d++) acc += tvw[d*4 + k] * W1[d*Dcst + e];
            g_WW1[k*Dcst + e] = acc;
        } else if (t < 640) {
            int e = t - 512;
            float bsum = 0.f;
            for (int d = 0; d < Dcst; d++) bsum += tvb[d] * W1[d*Dcst + e];
            g_bb1[e] = bsum;
        }
    } else if (blk == 3) {
        for (int i = t; i < 4*Hcst; i += 1024) g_S[i] = 0.f;
        if (t < Hcst) g_rowsum[t] = 0.f;
    } else if (blk < 68) {
        // tcw transpose: coalesced read, scattered 4B write
        int idx = (blk - 4)*1024 + t;        // 65536 total
        int d = idx >> 9, j = idx & 511;
        g_tcwT[j*Dcst + d] = tcw[idx];
    } else {
        // X4 transpose -> packed bf16x4, 4 b's per block (blocks 68..163)
        int sub = t >> 8, tl = t & 255;
        int b = (blk - 68)*4 + sub, n = b / TPcst, tp = b % TPcst;
        const float4* xr = (const float4*)(x + ((long)(n*192 + tp*4))*Hcst);
        float4 r0 = xr[tl], r1 = xr[256+tl], r2 = xr[512+tl], r3 = xr[768+tl];
        u64* dst = g_Xh + (long)b*Hcst + tl*4;
        dst[0] = pkbf4(r0.x, r1.x, r2.x, r3.x);
        dst[1] = pkbf4(r0.y, r1.y, r2.y, r3.y);
        dst[2] = pkbf4(r0.z, r1.z, r2.z, r3.z);
        dst[3] = pkbf4(r0.w, r1.w, r2.w, r3.w);
    }
}

// ================= k2 : transposed edge fill + projection tables =================
__global__ void __launch_bounds__(512) k2(const void* ed,
        const float* hemb, const float* wemb) {
    int t = threadIdx.x, blk = blockIdx.x;
    if (blk < 34) {
        // fill pkT (+rowsum, +S): 34 x 512 = 17408
        __shared__ int sflag;
        if (t == 0) sflag = 1;
        __syncthreads();
        if (t < 64) { if (((const int*)ed)[2*t+1] != 0) atomicAnd(&sflag, 0); }
        __syncthreads();
        int f = sflag;
        int i = blk*512 + t;
        int s, d;
        if (i < Ecst) {
            if (f) { s = (int)((const long long*)ed)[2L*i]; d = (int)((const long long*)ed)[2L*i+1]; }
            else   { s = ((const int*)ed)[2*i];             d = ((const int*)ed)[2*i+1]; }
        } else s = d = i - Ecst;
        float w = rsqrtf(g_deg[s]*g_deg[d]);
        int local = atomicAdd(&g_cursor[d], 1);
        unsigned cb = (unsigned)__bfloat16_as_ushort(__float2bfloat16(w));
        if (local < MAXDEG)
            g_pkT[local*Hcst + d] = (unsigned)s | (cb << 16);
        atomicAdd(&g_rowsum[d], w);
        atomicAdd(&g_S[g_invgrp[d]*Hcst + s], w * (1.f/256.f));
    } else {
        // projection tables: hpro (192 blocks: k*48+r), wpro (28 blocks: k*7+r)
        __shared__ float red[4][Dcst];
        int d = t & 127, cq = t >> 7;
        const float* emb; float* dst; int k, r, rows;
        int idx = blk - 34;
        if (idx < 192) { k = idx / 48; r = idx % 48; emb = hemb; dst = g_hpro; rows = 48; }
        else { idx -= 192; k = idx / 7; r = idx % 7; emb = wemb; dst = g_wpro; rows = 7; }
        float acc = 0.f;
        int c0 = cq*32;
        #pragma unroll 8
        for (int c = c0; c < c0+32; c++)
            acc += emb[r*Dcst + c] * g_tcwT[(4*c + k)*Dcst + d];
        red[cq][d] = acc;
        __syncthreads();
        if (cq == 0)
            dst[(k*rows + r)*Dcst + d] = red[0][d] + red[1][d] + red[2][d] + red[3][d];
    }
}

// ================= k3 : per-b gather + token + epilogue (incl. time) =================
__global__ void __launch_bounds__(256, 3) k3(const void* xm, const float* tcb,
        const float* b1, const float* W2, const float* b2, float* out) {
    __shared__ u64        sXh[Hcst];     // 8 KB
    __shared__ float      sY0[Hcst], sY1[Hcst], sY2[Hcst], sY3[Hcst];  // 16 KB
    __shared__ ulonglong2 sSI[Hcst];     // 16 KB
    __shared__ u64        sRSp[512];     // 4 KB
    __shared__ u64        sAcc[256][4];  // 8 KB
    __shared__ ulonglong2 sGM[128];      // 2 KB
    __shared__ int        sIdxH[4], sIdxW[4], sflag;

    int t = threadIdx.x, b = blockIdx.x;
    int n = b / TPcst, tp = b % TPcst;

    if (t == 0) sflag = 1;
    __syncthreads();
    if (t < 64) { if (((const int*)xm)[2*t+1] != 0) atomicAnd(&sflag, 0); }
    for (int i = t; i < Hcst; i += 256) {
        sXh[i] = g_Xh[(long)b*Hcst + i];
        ulonglong2 e;
        e.x = pk2(g_S[i],        g_S[Hcst+i]);
        e.y = pk2(g_S[2*Hcst+i], g_S[3*Hcst+i]);
        sSI[i] = e;
    }
    for (int vp = t; vp < 512; vp += 256)
        sRSp[vp] = pk2(g_rowsum[2*vp], g_rowsum[2*vp+1]);
    __syncthreads();
    if (t < 8) {
        int k = t & 3, isH = t >> 2;
        long base = ((long)(n*192 + tp*4 + k))*2 + isH;
        int v = sflag ? (int)((const long long*)xm)[base] : ((const int*)xm)[base];
        if (isH) sIdxH[k] = v; else sIdxW[k] = v;
    }

    // ---- gather: coalesced pkT reads, smem taps ----
    #pragma unroll
    for (int rep = 0; rep < 4; rep++) {
        int v = rep*256 + t;
        int dv = g_degi[v];
        float a0=0.f, a1=0.f, a2=0.f, a3=0.f;
        for (int e = 0; e < dv; e++) {
            unsigned p = g_pkT[e*Hcst + v];
            float w = __uint_as_float(p & 0xFFFF0000u);
            u64 xv = sXh[p & 1023u];
            float t0 = __uint_as_float((unsigned)(xv & 0xFFFFu) << 16);
            float t1 = __uint_as_float((unsigned)xv & 0xFFFF0000u);
            float t2 = __uint_as_float((unsigned)((xv >> 32) & 0xFFFFu) << 16);
            float t3 = __uint_as_float((unsigned)(xv >> 48) << 16);
            a0 += w*t0; a1 += w*t1; a2 += w*t2; a3 += w*t3;
        }
        sY0[v] = a0; sY1[v] = a1; sY2[v] = a2; sY3[v] = a3;
    }
    __syncthreads();

    // ---- token loop ----
    int dA = t & 63, dB = dA + 64;
    int q  = t >> 6;
    u64 W0A = pk2(g_WW1[dA],     g_WW1[dA]);
    u64 W1A = pk2(g_WW1[128+dA], g_WW1[128+dA]);
    u64 W2A = pk2(g_WW1[256+dA], g_WW1[256+dA]);
    u64 W3A = pk2(g_WW1[384+dA], g_WW1[384+dA]);
    u64 BBA = pk2(g_bb1[dA],     g_bb1[dA]);
    u64 B1A = pk2(b1[dA],        b1[dA]);
    u64 W0B = pk2(g_WW1[dB],     g_WW1[dB]);
    u64 W1B = pk2(g_WW1[128+dB], g_WW1[128+dB]);
    u64 W2B = pk2(g_WW1[256+dB], g_WW1[256+dB]);
    u64 W3B = pk2(g_WW1[384+dB], g_WW1[384+dB]);
    u64 BBB = pk2(g_bb1[dB],     g_bb1[dB]);
    u64 B1B = pk2(b1[dB],        b1[dB]);
    u64 a01A = 0, a23A = 0, a01B = 0, a23B = 0;
    int vp0 = q*128;
    #pragma unroll 2
    for (int vp = vp0; vp < vp0+128; vp++) {
        u64 yax = *(const u64*)&sY0[2*vp];
        u64 yay = *(const u64*)&sY1[2*vp];
        u64 ybx = *(const u64*)&sY2[2*vp];
        u64 yby = *(const u64*)&sY3[2*vp];
        u64 rsp = sRSp[vp];
        u64 hA = fma2(yax, W0A, B1A);
        hA = fma2(yay, W1A, hA);
        hA = fma2(ybx, W2A, hA);
        hA = fma2(yby, W3A, hA);
        hA = fma2(rsp, BBA, hA);
        u64 hB = fma2(yax, W0B, B1B);
        hB = fma2(yay, W1B, hB);
        hB = fma2(ybx, W2B, hB);
        hB = fma2(yby, W3B, hB);
        hB = fma2(rsp, BBB, hB);
        float ae, ao, be, bo;
        upk2(hA, ae, ao); upk2(hB, be, bo);
        ae = fmaxf(ae, 0.f); ao = fmaxf(ao, 0.f);
        be = fmaxf(be, 0.f); bo = fmaxf(bo, 0.f);
        u64 hAe = pk2(ae, ae), hAo = pk2(ao, ao);
        u64 hBe = pk2(be, be), hBo = pk2(bo, bo);
        ulonglong2 s0 = sSI[2*vp], s1 = sSI[2*vp+1];
        a01A = fma2(s0.x, hAe, a01A); a23A = fma2(s0.y, hAe, a23A);
        a01A = fma2(s1.x, hAo, a01A); a23A = fma2(s1.y, hAo, a23A);
        a01B = fma2(s0.x, hBe, a01B); a23B = fma2(s0.y, hBe, a23B);
        a01B = fma2(s1.x, hBo, a01B); a23B = fma2(s1.y, hBo, a23B);
    }
    sAcc[t][0] = a01A; sAcc[t][1] = a23A; sAcc[t][2] = a01B; sAcc[t][3] = a23B;
    __syncthreads();

    // ---- reduce quarters ----
    if (t < 128) {
        int d = t, lane = d & 63, hi = d >> 6;
        float g0=0.f, g1=0.f, g2=0.f, g3=0.f;
        #pragma unroll
        for (int qq = 0; qq < 4; qq++) {
            float x0, x1;
            upk2(sAcc[qq*64+lane][hi*2+0], x0, x1); g0 += x0; g1 += x1;
            upk2(sAcc[qq*64+lane][hi*2+1], x0, x1); g2 += x0; g3 += x1;
        }
        ulonglong2 e;
        e.x = pk2(g0, g1); e.y = pk2(g2, g3);
        sGM[d] = e;
    }
    __syncthreads();

    // ---- epilogue: out = gm @ W2 + b2 + time (from projected tables) ----
    if (t < 128) {
        int d = t;
        u64 o01 = 0, o23 = 0;
        #pragma unroll 4
        for (int c = 0; c < 128; c++) {
            ulonglong2 g = sGM[c];
            float w = __ldg(&W2[c*Dcst + d]);
            u64 ws = pk2(w, w);
            o01 = fma2(g.x, ws, o01);
            o23 = fma2(g.y, ws, o23);
        }
        float o0, o1, o2, o3;
        upk2(o01, o0, o1); upk2(o23, o2, o3);
        float tval = tcb[d];
        #pragma unroll
        for (int k = 0; k < 4; k++) {
            tval += g_hpro[(k*48 + sIdxH[k])*Dcst + d];
            tval += g_wpro[(k*7  + sIdxW[k])*Dcst + d];
        }
        long ob  = ((long)(n*192 + tp*4))*Dcst + d;
        long obh = OUTHALF + ob;
        out[obh] = tval; out[obh+128] = tval; out[obh+256] = tval; out[obh+384] = tval;
        float base = tval + b2[d];
        out[ob]     = o0 + base;
        out[ob+128] = o1 + base;
        out[ob+256] = o2 + base;
        out[ob+384] = o3 + base;
    }
}

// ---------------- launch ----------------
extern "C" void kernel_launch(void* const* d_in, const int* in_sizes, int n_in,
                              void* d_out, int out_size) {
    const float* x    = (const float*)d_in[0];
    const void*  xm   = d_in[1];
    const void*  ed   = d_in[2];
    const void*  ns   = d_in[3];
    const float* hemb = (const float*)d_in[4];
    const float* wemb = (const float*)d_in[5];
    const float* tcw  = (const float*)d_in[6];
    const float* tcb  = (const float*)d_in[7];
    const float* tvw  = (const float*)d_in[8];
    const float* tvb  = (const float*)d_in[9];
    const float* W1   = (const float*)d_in[10];
    const float* b1   = (const float*)d_in[11];
    const float* W2   = (const float*)d_in[12];
    const float* b2   = (const float*)d_in[13];
    float* out = (float*)d_out;

    k1<<<164, 1024>>>(ed, ns, x, tcw, tvw, tvb, W1);
    k2<<<254, 512>>>(ed, hemb, wemb);
    k3<<<NBcst, 256>>>(xm, tcb, b1, W2, b2, out);
}